// round 9
// baseline (speedup 1.0000x reference)
#include <cuda_runtime.h>
#include <cstdint>
#include <math.h>

#define B_ 32
#define T_ 1024
#define J_ 256
#define D_ 512

// ---------------- scratch (static device globals; no allocation) ------------
__device__ float g_S[B_ * T_ * J_];    // e = exp(S), unnormalized
__device__ float g_a[B_ * T_];         // ctx . w1
__device__ float g_c[B_ * J_];         // q . w2
__device__ float g_mp[2 * B_ * T_];    // rowmax partials (per n-block)
__device__ float g_zp[B_ * 8 * J_];    // column-sum partials (per t-block)
__device__ float g_zinv[B_ * J_];      // 1 / column sum
__device__ float g_bt[B_ * T_];        // softmax_t(rowmax)
__device__ float g_h[B_ * D_];         // sum_t bt * ctx

// ---------------- bf16 helpers ----------------------------------------------
__device__ __forceinline__ uint32_t bf2(float lo, float hi) {
    uint32_t r;
    asm("cvt.rn.bf16x2.f32 %0, %1, %2;" : "=r"(r) : "f"(hi), "f"(lo));
    return r;
}

#define MMA_BF16(c, a, bb)                                                      \
    asm("mma.sync.aligned.m16n8k16.row.col.f32.bf16.bf16.f32 "                  \
        "{%0,%1,%2,%3},{%4,%5,%6,%7},{%8,%9},{%0,%1,%2,%3};"                    \
        : "+f"((c)[0]), "+f"((c)[1]), "+f"((c)[2]), "+f"((c)[3])                \
        : "r"((a)[0]), "r"((a)[1]), "r"((a)[2]), "r"((a)[3]),                   \
          "r"((bb)[0]), "r"((bb)[1]))

// ---------------- kernel 1: a = ctx.w1, c = q.w2 ----------------------------
__global__ __launch_bounds__(256) void dotw_kernel(const float* __restrict__ ctx,
                                                   const float* __restrict__ q,
                                                   const float* __restrict__ w) {
    int gt = blockIdx.x * 256 + threadIdx.x;
    int gw = gt >> 5;
    int lane = gt & 31;
    if (gw >= B_ * T_ + B_ * J_) return;
    const float* rp;
    const float* wp;
    float* op;
    if (gw < B_ * T_) {
        rp = ctx + (size_t)gw * D_;
        wp = w;
        op = g_a + gw;
    } else {
        int r = gw - B_ * T_;
        rp = q + (size_t)r * D_;
        wp = w + D_;
        op = g_c + r;
    }
    const float4* r4 = (const float4*)rp;
    const float4* w4 = (const float4*)wp;
    float s = 0.f;
#pragma unroll
    for (int i = 0; i < 4; i++) {
        float4 x = r4[lane + i * 32];
        float4 ww = w4[lane + i * 32];
        s += x.x * ww.x + x.y * ww.y + x.z * ww.z + x.w * ww.w;
    }
#pragma unroll
    for (int off = 16; off > 0; off >>= 1) s += __shfl_xor_sync(0xffffffffu, s, off);
    if (lane == 0) *op = s;
}

// ---------------- kernel 2: GEMM1 + fused exp/rowmax/colsum -----------------
// S = (ctx*w3) @ q^T + a + c computed in registers; epilogue writes
// e = exp(S) to g_S, rowmax partials to g_mp, column-sum partials to g_zp.
__global__ __launch_bounds__(256) void gemm1_tc(const float* __restrict__ ctx,
                                                const float* __restrict__ q,
                                                const float* __restrict__ w) {
    __shared__ uint32_t As[2 * 8 * 128];   // [ka][matom][lane*4 + reg]
    __shared__ uint32_t Bs[2 * 16 * 64];   // [ka][natom][lane*2 + reg]
    __shared__ float w3s[D_];
    __shared__ float rmS[4][128];
    __shared__ float csS[128][17];

    const int tid = threadIdx.x;
    const int b = blockIdx.z;
    const int nb = blockIdx.x;
    const int m0 = blockIdx.y * 128;
    const int n0 = nb * 128;
    const float* Ag = ctx + (size_t)b * T_ * D_;
    const float* Bg = q + (size_t)b * J_ * D_;

    if (tid < 128) ((float4*)w3s)[tid] = ((const float4*)(w + 2 * D_))[tid];

    const int lane = tid & 31;
    const int wid = tid >> 5;
    const int warp_m = wid & 1;
    const int warp_n = wid >> 1;

    float acc[4][4][4];
#pragma unroll
    for (int i = 0; i < 4; i++)
#pragma unroll
        for (int j = 0; j < 4; j++)
#pragma unroll
            for (int k = 0; k < 4; k++) acc[i][j][k] = 0.f;

    float4 pa[4], pb[4];
#pragma unroll
    for (int i = 0; i < 4; i++) {
        int f = tid + i * 256;
        int m = f >> 3, k4 = f & 7;
        pa[i] = *(const float4*)(Ag + (size_t)(m0 + m) * D_ + k4 * 4);
        pb[i] = *(const float4*)(Bg + (size_t)(n0 + m) * D_ + k4 * 4);
    }
    __syncthreads();  // w3s ready

    const int KT = D_ / 32;
    for (int kt = 0; kt < KT; kt++) {
#pragma unroll
        for (int i = 0; i < 4; i++) {
            int f = tid + i * 256;
            int m = f >> 3, k4 = f & 7;
            int ka = k4 >> 2;
            int kl = (k4 & 3) * 4;           // local k within k16: 0,4,8,12
            int slot = (kl >> 1) & 3;        // 0 or 2
            // A scatter (w3-scaled, bf16 packed)
            {
                float4 v = pa[i];
                const float* wp = w3s + kt * 32 + k4 * 4;
                v.x *= wp[0]; v.y *= wp[1]; v.z *= wp[2]; v.w *= wp[3];
                int r = m & 15;
                uint32_t* dst = As + ((ka * 8 + (m >> 4)) << 7) +
                                ((r & 7) * 4 + slot) * 4 + (r >> 3) + ((kl >= 8) ? 2 : 0);
                dst[0] = bf2(v.x, v.y);
                dst[4] = bf2(v.z, v.w);
            }
            // B scatter
            {
                float4 v = pb[i];
                uint32_t* dst = Bs + ((ka * 16 + (m >> 3)) << 6) +
                                ((m & 7) * 4 + slot) * 2 + ((kl >= 8) ? 1 : 0);
                dst[0] = bf2(v.x, v.y);
                dst[2] = bf2(v.z, v.w);
            }
        }
        __syncthreads();
        if (kt + 1 < KT) {
#pragma unroll
            for (int i = 0; i < 4; i++) {
                int f = tid + i * 256;
                int m = f >> 3, k4 = f & 7;
                pa[i] = *(const float4*)(Ag + (size_t)(m0 + m) * D_ + (kt + 1) * 32 + k4 * 4);
                pb[i] = *(const float4*)(Bg + (size_t)(n0 + m) * D_ + (kt + 1) * 32 + k4 * 4);
            }
        }
#pragma unroll
        for (int ka = 0; ka < 2; ka++) {
            uint32_t af[4][4], bf[4][2];
#pragma unroll
            for (int ma = 0; ma < 4; ma++)
                *(uint4*)af[ma] = *(const uint4*)&As[((ka * 8 + warp_m * 4 + ma) << 7) + lane * 4];
#pragma unroll
            for (int na = 0; na < 4; na++)
                *(uint2*)bf[na] = *(const uint2*)&Bs[((ka * 16 + warp_n * 4 + na) << 6) + lane * 2];
#pragma unroll
            for (int ma = 0; ma < 4; ma++)
#pragma unroll
                for (int na = 0; na < 4; na++) MMA_BF16(acc[ma][na], af[ma], bf[na]);
        }
        __syncthreads();
    }

    // ---- fused epilogue: e = exp(S + a + c), rowmax + colsum partials ------
    const int g = lane >> 2;
    const int tg = lane & 3;
    float cn0[4][2];
#pragma unroll
    for (int na = 0; na < 4; na++) {
        int n = n0 + warp_n * 32 + na * 8 + tg * 2;
        cn0[na][0] = g_c[b * J_ + n];
        cn0[na][1] = g_c[b * J_ + n + 1];
    }
    float colsum[4][2];
#pragma unroll
    for (int na = 0; na < 4; na++) colsum[na][0] = colsum[na][1] = 0.f;

#pragma unroll
    for (int ma = 0; ma < 4; ma++) {
        int r0 = m0 + warp_m * 64 + ma * 16 + g;
        float a0v = g_a[b * T_ + r0];
        float a1v = g_a[b * T_ + r0 + 8];
        float rmax0 = -3.0e38f, rmax1 = -3.0e38f;
#pragma unroll
        for (int na = 0; na < 4; na++) {
            int n = n0 + warp_n * 32 + na * 8 + tg * 2;
            float s0 = acc[ma][na][0] + a0v + cn0[na][0];
            float s1 = acc[ma][na][1] + a0v + cn0[na][1];
            float s2 = acc[ma][na][2] + a1v + cn0[na][0];
            float s3 = acc[ma][na][3] + a1v + cn0[na][1];
            rmax0 = fmaxf(rmax0, fmaxf(s0, s1));
            rmax1 = fmaxf(rmax1, fmaxf(s2, s3));
            float e0 = __expf(s0), e1 = __expf(s1), e2 = __expf(s2), e3 = __expf(s3);
            colsum[na][0] += e0 + e2;
            colsum[na][1] += e1 + e3;
            float* p0 = g_S + (size_t)(b * T_ + r0) * J_ + n;
            *(float2*)p0 = make_float2(e0, e1);
            *(float2*)(p0 + 8 * J_) = make_float2(e2, e3);
        }
        // reduce rowmax over tg (4 lanes share a row)
        rmax0 = fmaxf(rmax0, __shfl_xor_sync(0xffffffffu, rmax0, 1));
        rmax0 = fmaxf(rmax0, __shfl_xor_sync(0xffffffffu, rmax0, 2));
        rmax1 = fmaxf(rmax1, __shfl_xor_sync(0xffffffffu, rmax1, 1));
        rmax1 = fmaxf(rmax1, __shfl_xor_sync(0xffffffffu, rmax1, 2));
        if (tg == 0) {
            rmS[warp_n][warp_m * 64 + ma * 16 + g] = rmax0;
            rmS[warp_n][warp_m * 64 + ma * 16 + 8 + g] = rmax1;
        }
    }
#pragma unroll
    for (int na = 0; na < 4; na++) {
#pragma unroll
        for (int c = 0; c < 2; c++)
            csS[warp_n * 32 + na * 8 + tg * 2 + c][warp_m * 8 + g] = colsum[na][c];
    }
    __syncthreads();
    if (tid < 128) {
        // rowmax partial across 4 warp_n
        float m = fmaxf(fmaxf(rmS[0][tid], rmS[1][tid]), fmaxf(rmS[2][tid], rmS[3][tid]));
        g_mp[nb * (B_ * T_) + b * T_ + m0 + tid] = m;
        // column-sum partial across 16 contributors
        float s = 0.f;
#pragma unroll
        for (int i = 0; i < 16; i++) s += csS[tid][i];
        g_zp[((size_t)b * 8 + blockIdx.y) * J_ + n0 + tid] = s;
    }
}

// ---------------- kernel 3: zinv = 1 / sum of column-sum partials -----------
__global__ __launch_bounds__(256) void zred_kernel() {
    const int b = blockIdx.x;
    const int j = threadIdx.x;
    float s = 0.f;
#pragma unroll
    for (int tb = 0; tb < 8; tb++) s += g_zp[((size_t)b * 8 + tb) * J_ + j];
    g_zinv[b * J_ + j] = 1.f / s;
}

// ---------------- kernel 4: b_t = softmax_t(rowmax) -------------------------
__global__ __launch_bounds__(256) void bt_kernel() {
    const int b = blockIdx.x;
    const int tid = threadIdx.x;
    const int lane = tid & 31;
    const int wid = tid >> 5;
    __shared__ float redA[8], redB[8];

    float4 v0 = ((const float4*)(g_mp + b * T_))[tid];
    float4 v1 = ((const float4*)(g_mp + B_ * T_ + b * T_))[tid];
    float4 v = make_float4(fmaxf(v0.x, v1.x), fmaxf(v0.y, v1.y),
                           fmaxf(v0.z, v1.z), fmaxf(v0.w, v1.w));
    float mx = fmaxf(fmaxf(v.x, v.y), fmaxf(v.z, v.w));
#pragma unroll
    for (int off = 16; off > 0; off >>= 1) mx = fmaxf(mx, __shfl_xor_sync(0xffffffffu, mx, off));
    if (lane == 0) redA[wid] = mx;
    __syncthreads();
    float bm = redA[0];
#pragma unroll
    for (int w = 1; w < 8; w++) bm = fmaxf(bm, redA[w]);

    float e0 = __expf(v.x - bm), e1 = __expf(v.y - bm);
    float e2 = __expf(v.z - bm), e3 = __expf(v.w - bm);
    float s = e0 + e1 + e2 + e3;
#pragma unroll
    for (int off = 16; off > 0; off >>= 1) s += __shfl_xor_sync(0xffffffffu, s, off);
    if (lane == 0) redB[wid] = s;
    __syncthreads();
    float tot = 0.f;
#pragma unroll
    for (int w = 0; w < 8; w++) tot += redB[w];
    float inv = 1.f / tot;
    ((float4*)(g_bt + b * T_))[tid] = make_float4(e0 * inv, e1 * inv, e2 * inv, e3 * inv);
}

// ---------------- kernel 6: h[b,d] = sum_t bt * ctx -------------------------
__global__ __launch_bounds__(256) void h_kernel(const float* __restrict__ ctx) {
    const int b = blockIdx.y;
    const int d = blockIdx.x * 256 + threadIdx.x;
    __shared__ float bts[T_];
    for (int i = threadIdx.x; i < T_; i += 256) bts[i] = g_bt[b * T_ + i];
    __syncthreads();
    const float* cp = ctx + (size_t)b * T_ * D_ + d;
    float acc = 0.f;
#pragma unroll 4
    for (int t = 0; t < T_; t++) acc += bts[t] * cp[(size_t)t * D_];
    g_h[b * D_ + d] = acc;
}

// ---------------- kernel 7: GEMM2  U = (e*zinv) @ q, fused G assembly -------
// A = unnormalized e; zinv folded into the bf16 A-scatter.
__global__ __launch_bounds__(256) void gemm2_tc(const float* __restrict__ ctx,
                                                const float* __restrict__ q,
                                                float* __restrict__ out) {
    __shared__ uint32_t As[2 * 8 * 128];
    __shared__ uint32_t Bs[2 * 16 * 64];
    __shared__ float zs[J_];

    const int tid = threadIdx.x;
    const int b = blockIdx.z;
    const int m0 = blockIdx.y * 128;
    const int n0 = blockIdx.x * 128;
    const float* Ag = g_S + (size_t)b * T_ * J_;  // e [1024][256]
    const float* Bg = q + (size_t)b * J_ * D_;    // [256][512], n contiguous

    const int lane = tid & 31;
    const int wid = tid >> 5;
    const int warp_m = wid & 1;
    const int warp_n = wid >> 1;

    zs[tid] = g_zinv[b * J_ + tid];

    float acc[4][4][4];
#pragma unroll
    for (int i = 0; i < 4; i++)
#pragma unroll
        for (int j = 0; j < 4; j++)
#pragma unroll
            for (int k = 0; k < 4; k++) acc[i][j][k] = 0.f;

    float4 pa[4];
    float4 pb0[2], pb1[2];
#pragma unroll
    for (int i = 0; i < 4; i++) {
        int f = tid + i * 256;
        int m = f >> 3, k4 = f & 7;
        pa[i] = *(const float4*)(Ag + (size_t)(m0 + m) * J_ + k4 * 4);
    }
#pragma unroll
    for (int i = 0; i < 2; i++) {
        int f = tid + i * 256;
        int kp = f >> 5, n4 = f & 31;
        pb0[i] = *(const float4*)(Bg + (size_t)(kp * 2) * D_ + n0 + n4 * 4);
        pb1[i] = *(const float4*)(Bg + (size_t)(kp * 2 + 1) * D_ + n0 + n4 * 4);
    }
    __syncthreads();  // zs ready

    const int KT = J_ / 32;
    for (int kt = 0; kt < KT; kt++) {
        // A scatter (zinv-normalized, bf16 packed)
#pragma unroll
        for (int i = 0; i < 4; i++) {
            int f = tid + i * 256;
            int m = f >> 3, k4 = f & 7;
            int ka = k4 >> 2;
            int kl = (k4 & 3) * 4;
            int slot = (kl >> 1) & 3;
            float4 v = pa[i];
            const float* zp = zs + kt * 32 + k4 * 4;
            v.x *= zp[0]; v.y *= zp[1]; v.z *= zp[2]; v.w *= zp[3];
            int r = m & 15;
            uint32_t* dst = As + ((ka * 8 + (m >> 4)) << 7) +
                            ((r & 7) * 4 + slot) * 4 + (r >> 3) + ((kl >= 8) ? 2 : 0);
            dst[0] = bf2(v.x, v.y);
            dst[4] = bf2(v.z, v.w);
        }
        // B scatter: k-pair rows packed into bf16x2 along k
#pragma unroll
        for (int i = 0; i < 2; i++) {
            int f = tid + i * 256;
            int kp = f >> 5, n4 = f & 31;   // kp in [0,16), n4 in [0,32)
            int ka = kp >> 3;
            int pl = kp & 7;
            int slot = pl & 3;
            int regk = pl >> 2;
            const float* r0 = &pb0[i].x;
            const float* r1 = &pb1[i].x;
#pragma unroll
            for (int jj = 0; jj < 4; jj++) {
                int n = n4 * 4 + jj;
                uint32_t* dst = Bs + ((ka * 16 + (n >> 3)) << 6) +
                                ((n & 7) * 4 + slot) * 2 + regk;
                dst[0] = bf2(r0[jj], r1[jj]);
            }
        }
        __syncthreads();
        if (kt + 1 < KT) {
#pragma unroll
            for (int i = 0; i < 4; i++) {
                int f = tid + i * 256;
                int m = f >> 3, k4 = f & 7;
                pa[i] = *(const float4*)(Ag + (size_t)(m0 + m) * J_ + (kt + 1) * 32 + k4 * 4);
            }
#pragma unroll
            for (int i = 0; i < 2; i++) {
                int f = tid + i * 256;
                int kp = f >> 5, n4 = f & 31;
                pb0[i] = *(const float4*)(Bg + (size_t)((kt + 1) * 32 + kp * 2) * D_ + n0 + n4 * 4);
                pb1[i] = *(const float4*)(Bg + (size_t)((kt + 1) * 32 + kp * 2 + 1) * D_ + n0 + n4 * 4);
            }
        }
#pragma unroll
        for (int ka = 0; ka < 2; ka++) {
            uint32_t af[4][4], bf[4][2];
#pragma unroll
            for (int ma = 0; ma < 4; ma++)
                *(uint4*)af[ma] = *(const uint4*)&As[((ka * 8 + warp_m * 4 + ma) << 7) + lane * 4];
#pragma unroll
            for (int na = 0; na < 4; na++)
                *(uint2*)bf[na] = *(const uint2*)&Bs[((ka * 16 + warp_n * 4 + na) << 6) + lane * 2];
#pragma unroll
            for (int ma = 0; ma < 4; ma++)
#pragma unroll
                for (int na = 0; na < 4; na++) MMA_BF16(acc[ma][na], af[ma], bf[na]);
        }
        __syncthreads();
    }

    // epilogue: G = [ctx | U | ctx*U | ctx*h]
    const int g = lane >> 2;
    const int tg = lane & 3;
#pragma unroll
    for (int ma = 0; ma < 4; ma++) {
        int r0 = m0 + warp_m * 64 + ma * 16 + g;
#pragma unroll
        for (int rr = 0; rr < 2; rr++) {
            int m = r0 + rr * 8;
            const float* crow = ctx + ((size_t)(b * T_ + m)) * D_;
            float* orow = out + ((size_t)(b * T_ + m)) * (4 * D_);
#pragma unroll
            for (int na = 0; na < 4; na++) {
                int n = n0 + warp_n * 32 + na * 8 + tg * 2;
                float2 cv = *(const float2*)(crow + n);
                float2 hv = *(const float2*)(g_h + b * D_ + n);
                float u0 = acc[ma][na][rr * 2 + 0];
                float u1 = acc[ma][na][rr * 2 + 1];
                *(float2*)(orow + n) = cv;
                *(float2*)(orow + D_ + n) = make_float2(u0, u1);
                *(float2*)(orow + 2 * D_ + n) = make_float2(cv.x * u0, cv.y * u1);
                *(float2*)(orow + 3 * D_ + n) = make_float2(cv.x * hv.x, cv.y * hv.y);
            }
        }
    }
}

// ---------------- launch -----------------------------------------------------
extern "C" void kernel_launch(void* const* d_in, const int* in_sizes, int n_in,
                              void* d_out, int out_size) {
    const float* ctx = (const float*)d_in[0];
    const float* q = (const float*)d_in[1];
    const float* w = (const float*)d_in[2];
    float* out = (float*)d_out;

    dotw_kernel<<<5120, 256>>>(ctx, q, w);
    gemm1_tc<<<dim3(2, 8, 32), 256>>>(ctx, q, w);
    zred_kernel<<<32, 256>>>();
    bt_kernel<<<32, 256>>>();
    h_kernel<<<dim3(2, 32), 256>>>(ctx);
    gemm2_tc<<<dim3(4, 8, 32), 256>>>(ctx, q, out);
}

// round 10
// speedup vs baseline: 1.3446x; 1.3446x over previous
#include <cuda_runtime.h>
#include <cstdint>
#include <math.h>

#define B_ 32
#define T_ 1024
#define J_ 256
#define D_ 512

// ---------------- scratch (static device globals; no allocation) ------------
__device__ float g_S[B_ * T_ * J_];    // S, then e = exp(S) (unnormalized)
__device__ float g_a[B_ * T_];         // ctx . w1
__device__ float g_c[B_ * J_];         // q . w2
__device__ float g_m[B_ * T_];         // rowmax over j
__device__ float g_zp[B_ * 8 * J_];    // column-sum partials (per t-block)
__device__ float g_zinv[B_ * J_];      // 1 / column sum
__device__ float g_bt[B_ * T_];        // softmax_t(rowmax)
__device__ float g_h[B_ * D_];         // sum_t bt * ctx

// ---------------- bf16 helpers ----------------------------------------------
__device__ __forceinline__ uint32_t bf2(float lo, float hi) {
    uint32_t r;
    asm("cvt.rn.bf16x2.f32 %0, %1, %2;" : "=r"(r) : "f"(hi), "f"(lo));
    return r;
}

#define MMA_BF16(c, a, bb)                                                      \
    asm("mma.sync.aligned.m16n8k16.row.col.f32.bf16.bf16.f32 "                  \
        "{%0,%1,%2,%3},{%4,%5,%6,%7},{%8,%9},{%0,%1,%2,%3};"                    \
        : "+f"((c)[0]), "+f"((c)[1]), "+f"((c)[2]), "+f"((c)[3])                \
        : "r"((a)[0]), "r"((a)[1]), "r"((a)[2]), "r"((a)[3]),                   \
          "r"((bb)[0]), "r"((bb)[1]))

// ---------------- kernel 1: a = ctx.w1, c = q.w2 ----------------------------
__global__ __launch_bounds__(256) void dotw_kernel(const float* __restrict__ ctx,
                                                   const float* __restrict__ q,
                                                   const float* __restrict__ w) {
    int gt = blockIdx.x * 256 + threadIdx.x;
    int gw = gt >> 5;
    int lane = gt & 31;
    if (gw >= B_ * T_ + B_ * J_) return;
    const float* rp;
    const float* wp;
    float* op;
    if (gw < B_ * T_) {
        rp = ctx + (size_t)gw * D_;
        wp = w;
        op = g_a + gw;
    } else {
        int r = gw - B_ * T_;
        rp = q + (size_t)r * D_;
        wp = w + D_;
        op = g_c + r;
    }
    const float4* r4 = (const float4*)rp;
    const float4* w4 = (const float4*)wp;
    float s = 0.f;
#pragma unroll
    for (int i = 0; i < 4; i++) {
        float4 x = r4[lane + i * 32];
        float4 ww = w4[lane + i * 32];
        s += x.x * ww.x + x.y * ww.y + x.z * ww.z + x.w * ww.w;
    }
#pragma unroll
    for (int off = 16; off > 0; off >>= 1) s += __shfl_xor_sync(0xffffffffu, s, off);
    if (lane == 0) *op = s;
}

// ---------------- kernel 2: GEMM1  S = (ctx*w3) @ q^T + a + c  (bf16 mma) ---
// EXACT R8 version (register budget untouched).
__global__ __launch_bounds__(256) void gemm1_tc(const float* __restrict__ ctx,
                                                const float* __restrict__ q,
                                                const float* __restrict__ w) {
    __shared__ uint32_t As[2 * 8 * 128];   // [ka][matom][lane*4 + reg]
    __shared__ uint32_t Bs[2 * 16 * 64];   // [ka][natom][lane*2 + reg]
    __shared__ float w3s[D_];

    const int tid = threadIdx.x;
    const int b = blockIdx.z;
    const int m0 = blockIdx.y * 128;
    const int n0 = blockIdx.x * 128;
    const float* Ag = ctx + (size_t)b * T_ * D_;
    const float* Bg = q + (size_t)b * J_ * D_;

    if (tid < 128) ((float4*)w3s)[tid] = ((const float4*)(w + 2 * D_))[tid];

    const int lane = tid & 31;
    const int wid = tid >> 5;
    const int warp_m = wid & 1;
    const int warp_n = wid >> 1;

    float acc[4][4][4];
#pragma unroll
    for (int i = 0; i < 4; i++)
#pragma unroll
        for (int j = 0; j < 4; j++)
#pragma unroll
            for (int k = 0; k < 4; k++) acc[i][j][k] = 0.f;

    float4 pa[4], pb[4];
#pragma unroll
    for (int i = 0; i < 4; i++) {
        int f = tid + i * 256;
        int m = f >> 3, k4 = f & 7;
        pa[i] = *(const float4*)(Ag + (size_t)(m0 + m) * D_ + k4 * 4);
        pb[i] = *(const float4*)(Bg + (size_t)(n0 + m) * D_ + k4 * 4);
    }
    __syncthreads();  // w3s ready

    const int KT = D_ / 32;
    for (int kt = 0; kt < KT; kt++) {
#pragma unroll
        for (int i = 0; i < 4; i++) {
            int f = tid + i * 256;
            int m = f >> 3, k4 = f & 7;
            int ka = k4 >> 2;
            int kl = (k4 & 3) * 4;           // local k within k16: 0,4,8,12
            int slot = (kl >> 1) & 3;        // 0 or 2
            // A scatter (w3-scaled, bf16 packed)
            {
                float4 v = pa[i];
                const float* wp = w3s + kt * 32 + k4 * 4;
                v.x *= wp[0]; v.y *= wp[1]; v.z *= wp[2]; v.w *= wp[3];
                int r = m & 15;
                uint32_t* dst = As + ((ka * 8 + (m >> 4)) << 7) +
                                ((r & 7) * 4 + slot) * 4 + (r >> 3) + ((kl >= 8) ? 2 : 0);
                dst[0] = bf2(v.x, v.y);
                dst[4] = bf2(v.z, v.w);
            }
            // B scatter
            {
                float4 v = pb[i];
                uint32_t* dst = Bs + ((ka * 16 + (m >> 3)) << 6) +
                                ((m & 7) * 4 + slot) * 2 + ((kl >= 8) ? 1 : 0);
                dst[0] = bf2(v.x, v.y);
                dst[2] = bf2(v.z, v.w);
            }
        }
        __syncthreads();
        if (kt + 1 < KT) {
#pragma unroll
            for (int i = 0; i < 4; i++) {
                int f = tid + i * 256;
                int m = f >> 3, k4 = f & 7;
                pa[i] = *(const float4*)(Ag + (size_t)(m0 + m) * D_ + (kt + 1) * 32 + k4 * 4);
                pb[i] = *(const float4*)(Bg + (size_t)(n0 + m) * D_ + (kt + 1) * 32 + k4 * 4);
            }
        }
#pragma unroll
        for (int ka = 0; ka < 2; ka++) {
            uint32_t af[4][4], bf[4][2];
#pragma unroll
            for (int ma = 0; ma < 4; ma++)
                *(uint4*)af[ma] = *(const uint4*)&As[((ka * 8 + warp_m * 4 + ma) << 7) + lane * 4];
#pragma unroll
            for (int na = 0; na < 4; na++)
                *(uint2*)bf[na] = *(const uint2*)&Bs[((ka * 16 + warp_n * 4 + na) << 6) + lane * 2];
#pragma unroll
            for (int ma = 0; ma < 4; ma++)
#pragma unroll
                for (int na = 0; na < 4; na++) MMA_BF16(acc[ma][na], af[ma], bf[na]);
        }
        __syncthreads();
    }

    // epilogue: + a[b,m] + c[b,n]
    const int g = lane >> 2;
    const int tg = lane & 3;
#pragma unroll
    for (int ma = 0; ma < 4; ma++) {
        int r0 = m0 + warp_m * 64 + ma * 16 + g;
        float a0v = g_a[b * T_ + r0];
        float a1v = g_a[b * T_ + r0 + 8];
#pragma unroll
        for (int na = 0; na < 4; na++) {
            int n = n0 + warp_n * 32 + na * 8 + tg * 2;
            float c0 = g_c[b * J_ + n];
            float c1 = g_c[b * J_ + n + 1];
            float* p0 = g_S + (size_t)(b * T_ + r0) * J_ + n;
            *(float2*)p0 = make_float2(acc[ma][na][0] + a0v + c0, acc[ma][na][1] + a0v + c1);
            *(float2*)(p0 + 8 * J_) =
                make_float2(acc[ma][na][2] + a1v + c0, acc[ma][na][3] + a1v + c1);
        }
    }
}

// ---------------- kernel 3: e = exp(S), rowmax -> g_m, colsum partials ------
// One read + one write of S. Each warp owns full rows (256 j per row).
// Block = (t-block of 128 rows) x b; 8 warps, warp handles rows wrp + 8r.
__global__ __launch_bounds__(256) void expred_kernel() {
    const int b = blockIdx.y;
    const int tb = blockIdx.x;  // 0..7
    const int lane = threadIdx.x & 31;
    const int wrp = threadIdx.x >> 5;
    float* S = g_S + (size_t)b * T_ * J_;
    __shared__ float csS[8][J_];

    float cs0[4] = {0.f, 0.f, 0.f, 0.f};
    float cs1[4] = {0.f, 0.f, 0.f, 0.f};
#pragma unroll 4
    for (int r = 0; r < 16; r++) {
        int t = tb * 128 + r * 8 + wrp;
        float* row = S + (size_t)t * J_;
        float4 v0 = *(float4*)(row + lane * 4);
        float4 v1 = *(float4*)(row + 128 + lane * 4);
        float mx = fmaxf(fmaxf(fmaxf(v0.x, v0.y), fmaxf(v0.z, v0.w)),
                         fmaxf(fmaxf(v1.x, v1.y), fmaxf(v1.z, v1.w)));
#pragma unroll
        for (int off = 16; off > 0; off >>= 1)
            mx = fmaxf(mx, __shfl_xor_sync(0xffffffffu, mx, off));
        if (lane == 0) g_m[b * T_ + t] = mx;
        float4 e0 = make_float4(__expf(v0.x), __expf(v0.y), __expf(v0.z), __expf(v0.w));
        float4 e1 = make_float4(__expf(v1.x), __expf(v1.y), __expf(v1.z), __expf(v1.w));
        *(float4*)(row + lane * 4) = e0;
        *(float4*)(row + 128 + lane * 4) = e1;
        cs0[0] += e0.x; cs0[1] += e0.y; cs0[2] += e0.z; cs0[3] += e0.w;
        cs1[0] += e1.x; cs1[1] += e1.y; cs1[2] += e1.z; cs1[3] += e1.w;
    }
#pragma unroll
    for (int i = 0; i < 4; i++) {
        csS[wrp][lane * 4 + i] = cs0[i];
        csS[wrp][128 + lane * 4 + i] = cs1[i];
    }
    __syncthreads();
    // one thread per j sums the 8 warps' partials
    float s = 0.f;
#pragma unroll
    for (int wq = 0; wq < 8; wq++) s += csS[wq][threadIdx.x];
    g_zp[((size_t)b * 8 + tb) * J_ + threadIdx.x] = s;
}

// ---------------- kernel 3b: zinv = 1 / sum of partials ---------------------
__global__ __launch_bounds__(256) void zred_kernel() {
    const int b = blockIdx.x;
    const int j = threadIdx.x;
    float s = 0.f;
#pragma unroll
    for (int tb = 0; tb < 8; tb++) s += g_zp[((size_t)b * 8 + tb) * J_ + j];
    g_zinv[b * J_ + j] = 1.f / s;
}

// ---------------- kernel 4: b_t = softmax_t(rowmax) -------------------------
__global__ __launch_bounds__(256) void bt_kernel() {
    const int b = blockIdx.x;
    const int tid = threadIdx.x;
    const int lane = tid & 31;
    const int wid = tid >> 5;
    __shared__ float redA[8], redB[8];

    float4 v = ((const float4*)(g_m + b * T_))[tid];
    float mx = fmaxf(fmaxf(v.x, v.y), fmaxf(v.z, v.w));
#pragma unroll
    for (int off = 16; off > 0; off >>= 1) mx = fmaxf(mx, __shfl_xor_sync(0xffffffffu, mx, off));
    if (lane == 0) redA[wid] = mx;
    __syncthreads();
    float bm = redA[0];
#pragma unroll
    for (int w = 1; w < 8; w++) bm = fmaxf(bm, redA[w]);

    float e0 = __expf(v.x - bm), e1 = __expf(v.y - bm);
    float e2 = __expf(v.z - bm), e3 = __expf(v.w - bm);
    float s = e0 + e1 + e2 + e3;
#pragma unroll
    for (int off = 16; off > 0; off >>= 1) s += __shfl_xor_sync(0xffffffffu, s, off);
    if (lane == 0) redB[wid] = s;
    __syncthreads();
    float tot = 0.f;
#pragma unroll
    for (int w = 0; w < 8; w++) tot += redB[w];
    float inv = 1.f / tot;
    ((float4*)(g_bt + b * T_))[tid] = make_float4(e0 * inv, e1 * inv, e2 * inv, e3 * inv);
}

// ---------------- kernel 6: h[b,d] = sum_t bt * ctx -------------------------
__global__ __launch_bounds__(256) void h_kernel(const float* __restrict__ ctx) {
    const int b = blockIdx.y;
    const int d = blockIdx.x * 256 + threadIdx.x;
    __shared__ float bts[T_];
    for (int i = threadIdx.x; i < T_; i += 256) bts[i] = g_bt[b * T_ + i];
    __syncthreads();
    const float* cp = ctx + (size_t)b * T_ * D_ + d;
    float acc = 0.f;
#pragma unroll 4
    for (int t = 0; t < T_; t++) acc += bts[t] * cp[(size_t)t * D_];
    g_h[b * D_ + d] = acc;
}

// ---------------- kernel 7: GEMM2  U = e @ (zinv*q), fused G assembly -------
// A = unnormalized e; zinv folded into the B (q) scatter: Bhat[k,n]=q[k,n]*zinv[k].
__global__ __launch_bounds__(256) void gemm2_tc(const float* __restrict__ ctx,
                                                const float* __restrict__ q,
                                                float* __restrict__ out) {
    __shared__ uint32_t As[2 * 8 * 128];
    __shared__ uint32_t Bs[2 * 16 * 64];
    __shared__ float zs[J_];

    const int tid = threadIdx.x;
    const int b = blockIdx.z;
    const int m0 = blockIdx.y * 128;
    const int n0 = blockIdx.x * 128;
    const float* Ag = g_S + (size_t)b * T_ * J_;  // e [1024][256]
    const float* Bg = q + (size_t)b * J_ * D_;    // [256][512], n contiguous

    const int lane = tid & 31;
    const int wid = tid >> 5;
    const int warp_m = wid & 1;
    const int warp_n = wid >> 1;

    zs[tid] = g_zinv[b * J_ + tid];

    float acc[4][4][4];
#pragma unroll
    for (int i = 0; i < 4; i++)
#pragma unroll
        for (int j = 0; j < 4; j++)
#pragma unroll
            for (int k = 0; k < 4; k++) acc[i][j][k] = 0.f;

    float4 pa[4];
    float4 pb0[2], pb1[2];
#pragma unroll
    for (int i = 0; i < 4; i++) {
        int f = tid + i * 256;
        int m = f >> 3, k4 = f & 7;
        pa[i] = *(const float4*)(Ag + (size_t)(m0 + m) * J_ + k4 * 4);
    }
#pragma unroll
    for (int i = 0; i < 2; i++) {
        int f = tid + i * 256;
        int kp = f >> 5, n4 = f & 31;
        pb0[i] = *(const float4*)(Bg + (size_t)(kp * 2) * D_ + n0 + n4 * 4);
        pb1[i] = *(const float4*)(Bg + (size_t)(kp * 2 + 1) * D_ + n0 + n4 * 4);
    }
    __syncthreads();  // zs ready

    const int KT = J_ / 32;
    for (int kt = 0; kt < KT; kt++) {
        // A scatter (bf16 packed, raw e)
#pragma unroll
        for (int i = 0; i < 4; i++) {
            int f = tid + i * 256;
            int m = f >> 3, k4 = f & 7;
            int ka = k4 >> 2;
            int kl = (k4 & 3) * 4;
            int slot = (kl >> 1) & 3;
            float4 v = pa[i];
            int r = m & 15;
            uint32_t* dst = As + ((ka * 8 + (m >> 4)) << 7) +
                            ((r & 7) * 4 + slot) * 4 + (r >> 3) + ((kl >= 8) ? 2 : 0);
            dst[0] = bf2(v.x, v.y);
            dst[4] = bf2(v.z, v.w);
        }
        // B scatter: k-pair rows, scaled by zinv[k], packed bf16x2 along k
#pragma unroll
        for (int i = 0; i < 2; i++) {
            int f = tid + i * 256;
            int kp = f >> 5, n4 = f & 31;   // kp in [0,16), n4 in [0,32)
            int ka = kp >> 3;
            int pl = kp & 7;
            int slot = pl & 3;
            int regk = pl >> 2;
            float z0 = zs[kt * 32 + kp * 2];
            float z1 = zs[kt * 32 + kp * 2 + 1];
            const float* r0 = &pb0[i].x;
            const float* r1 = &pb1[i].x;
#pragma unroll
            for (int jj = 0; jj < 4; jj++) {
                int n = n4 * 4 + jj;
                uint32_t* dst = Bs + ((ka * 16 + (n >> 3)) << 6) +
                                ((n & 7) * 4 + slot) * 2 + regk;
                dst[0] = bf2(r0[jj] * z0, r1[jj] * z1);
            }
        }
        __syncthreads();
        if (kt + 1 < KT) {
#pragma unroll
            for (int i = 0; i < 4; i++) {
                int f = tid + i * 256;
                int m = f >> 3, k4 = f & 7;
                pa[i] = *(const float4*)(Ag + (size_t)(m0 + m) * J_ + (kt + 1) * 32 + k4 * 4);
            }
#pragma unroll
            for (int i = 0; i < 2; i++) {
                int f = tid + i * 256;
                int kp = f >> 5, n4 = f & 31;
                pb0[i] = *(const float4*)(Bg + (size_t)((kt + 1) * 32 + kp * 2) * D_ + n0 + n4 * 4);
                pb1[i] = *(const float4*)(Bg + (size_t)((kt + 1) * 32 + kp * 2 + 1) * D_ + n0 + n4 * 4);
            }
        }
#pragma unroll
        for (int ka = 0; ka < 2; ka++) {
            uint32_t af[4][4], bf[4][2];
#pragma unroll
            for (int ma = 0; ma < 4; ma++)
                *(uint4*)af[ma] = *(const uint4*)&As[((ka * 8 + warp_m * 4 + ma) << 7) + lane * 4];
#pragma unroll
            for (int na = 0; na < 4; na++)
                *(uint2*)bf[na] = *(const uint2*)&Bs[((ka * 16 + warp_n * 4 + na) << 6) + lane * 2];
#pragma unroll
            for (int ma = 0; ma < 4; ma++)
#pragma unroll
                for (int na = 0; na < 4; na++) MMA_BF16(acc[ma][na], af[ma], bf[na]);
        }
        __syncthreads();
    }

    // epilogue: G = [ctx | U | ctx*U | ctx*h]
    const int g = lane >> 2;
    const int tg = lane & 3;
#pragma unroll
    for (int ma = 0; ma < 4; ma++) {
        int r0 = m0 + warp_m * 64 + ma * 16 + g;
#pragma unroll
        for (int rr = 0; rr < 2; rr++) {
            int m = r0 + rr * 8;
            const float* crow = ctx + ((size_t)(b * T_ + m)) * D_;
            float* orow = out + ((size_t)(b * T_ + m)) * (4 * D_);
#pragma unroll
            for (int na = 0; na < 4; na++) {
                int n = n0 + warp_n * 32 + na * 8 + tg * 2;
                float2 cv = *(const float2*)(crow + n);
                float2 hv = *(const float2*)(g_h + b * D_ + n);
                float u0 = acc[ma][na][rr * 2 + 0];
                float u1 = acc[ma][na][rr * 2 + 1];
                *(float2*)(orow + n) = cv;
                *(float2*)(orow + D_ + n) = make_float2(u0, u1);
                *(float2*)(orow + 2 * D_ + n) = make_float2(cv.x * u0, cv.y * u1);
                *(float2*)(orow + 3 * D_ + n) = make_float2(cv.x * hv.x, cv.y * hv.y);
            }
        }
    }
}

// ---------------- launch -----------------------------------------------------
extern "C" void kernel_launch(void* const* d_in, const int* in_sizes, int n_in,
                              void* d_out, int out_size) {
    const float* ctx = (const float*)d_in[0];
    const float* q = (const float*)d_in[1];
    const float* w = (const float*)d_in[2];
    float* out = (float*)d_out;

    dotw_kernel<<<5120, 256>>>(ctx, q, w);
    gemm1_tc<<<dim3(2, 8, 32), 256>>>(ctx, q, w);
    expred_kernel<<<dim3(8, 32), 256>>>();
    zred_kernel<<<32, 256>>>();
    bt_kernel<<<32, 256>>>();
    h_kernel<<<dim3(2, 32), 256>>>(ctx);
    gemm2_tc<<<dim3(4, 8, 32), 256>>>(ctx, q, out);
}

// round 11
// speedup vs baseline: 1.5910x; 1.1833x over previous
#include <cuda_runtime.h>
#include <cstdint>
#include <math.h>

#define B_ 32
#define T_ 1024
#define J_ 256
#define D_ 512

// ---------------- scratch (static device globals; no allocation) ------------
__device__ float g_S[B_ * T_ * J_];       // S, then e = exp(S) (unnormalized)
__device__ float g_a[B_ * T_];            // ctx . w1
__device__ float g_c[B_ * J_];            // q . w2
__device__ float g_m[B_ * T_];            // rowmax over j
__device__ float g_zp[B_ * 8 * J_];       // column-sum partials (per t-block)
__device__ float g_zinv[B_ * J_];         // 1 / column sum
__device__ float g_bt[B_ * T_];           // softmax_t(rowmax)
__device__ float g_h[B_ * D_];            // sum_t bt * ctx
// bf16 fragment images (exact SMEM word layout per (block, k-tile) chunk)
__device__ uint32_t g_ap[B_ * 8 * 16 * 2048];  // gemm1 A: (b, mb, kt) chunks
__device__ uint32_t g_qp[B_ * 4 * 8 * 2048];   // gemm2 B: (b, nb, kt) chunks

// ---------------- bf16 helpers ----------------------------------------------
__device__ __forceinline__ uint32_t bf2(float lo, float hi) {
    uint32_t r;
    asm("cvt.rn.bf16x2.f32 %0, %1, %2;" : "=r"(r) : "f"(hi), "f"(lo));
    return r;
}

#define MMA_BF16(c, a, bb)                                                      \
    asm("mma.sync.aligned.m16n8k16.row.col.f32.bf16.bf16.f32 "                  \
        "{%0,%1,%2,%3},{%4,%5,%6,%7},{%8,%9},{%0,%1,%2,%3};"                    \
        : "+f"((c)[0]), "+f"((c)[1]), "+f"((c)[2]), "+f"((c)[3])                \
        : "r"((a)[0]), "r"((a)[1]), "r"((a)[2]), "r"((a)[3]),                   \
          "r"((bb)[0]), "r"((bb)[1]))

// ---------------- kernel 1: a = ctx.w1, c = q.w2 ----------------------------
__global__ __launch_bounds__(256) void dotw_kernel(const float* __restrict__ ctx,
                                                   const float* __restrict__ q,
                                                   const float* __restrict__ w) {
    int gt = blockIdx.x * 256 + threadIdx.x;
    int gw = gt >> 5;
    int lane = gt & 31;
    if (gw >= B_ * T_ + B_ * J_) return;
    const float* rp;
    const float* wp;
    float* op;
    if (gw < B_ * T_) {
        rp = ctx + (size_t)gw * D_;
        wp = w;
        op = g_a + gw;
    } else {
        int r = gw - B_ * T_;
        rp = q + (size_t)r * D_;
        wp = w + D_;
        op = g_c + r;
    }
    const float4* r4 = (const float4*)rp;
    const float4* w4 = (const float4*)wp;
    float s = 0.f;
#pragma unroll
    for (int i = 0; i < 4; i++) {
        float4 x = r4[lane + i * 32];
        float4 ww = w4[lane + i * 32];
        s += x.x * ww.x + x.y * ww.y + x.z * ww.z + x.w * ww.w;
    }
#pragma unroll
    for (int off = 16; off > 0; off >>= 1) s += __shfl_xor_sync(0xffffffffu, s, off);
    if (lane == 0) *op = s;
}

// ---------------- kernel 1b: apack — ctx*w3 -> bf16 A fragments -------------
// Chunk (b, mb, kt) = 2048 words, word layout identical to gemm1's old As.
__global__ __launch_bounds__(256) void apack_kernel(const float* __restrict__ ctx,
                                                    const float* __restrict__ w) {
    __shared__ float w3s[32];
    const int kt = blockIdx.x;
    const int mb = blockIdx.y;
    const int b = blockIdx.z;
    const int tid = threadIdx.x;
    if (tid < 8) ((float4*)w3s)[tid] = ((const float4*)(w + 2 * D_ + kt * 32))[tid];
    __syncthreads();
    const float* Ag = ctx + (size_t)b * T_ * D_ + (size_t)mb * 128 * D_ + kt * 32;
    uint32_t* chunk = g_ap + (((size_t)(b * 8 + mb) * 16) + kt) * 2048;
#pragma unroll
    for (int i = 0; i < 4; i++) {
        int f = tid + i * 256;
        int m = f >> 3, k4 = f & 7;
        int ka = k4 >> 2;
        int kl = (k4 & 3) * 4;
        int slot = (kl >> 1) & 3;
        float4 v = *(const float4*)(Ag + (size_t)m * D_ + k4 * 4);
        v.x *= w3s[k4 * 4 + 0];
        v.y *= w3s[k4 * 4 + 1];
        v.z *= w3s[k4 * 4 + 2];
        v.w *= w3s[k4 * 4 + 3];
        int r = m & 15;
        uint32_t* dst = chunk + ((ka * 8 + (m >> 4)) << 7) +
                        ((r & 7) * 4 + slot) * 4 + (r >> 3) + ((kl >= 8) ? 2 : 0);
        dst[0] = bf2(v.x, v.y);
        dst[4] = bf2(v.z, v.w);
    }
}

// ---------------- kernel 1c: qpack — q -> bf16 B fragments (gemm2 layout) ---
__global__ __launch_bounds__(256) void qpack_kernel(const float* __restrict__ q) {
    const int kt = blockIdx.x;   // 0..7
    const int nb = blockIdx.y;   // 0..3
    const int b = blockIdx.z;
    const int tid = threadIdx.x;
    const float* Bg = q + (size_t)b * J_ * D_ + (size_t)kt * 32 * D_ + nb * 128;
    uint32_t* chunk = g_qp + (((size_t)(b * 4 + nb) * 8) + kt) * 2048;
#pragma unroll
    for (int i = 0; i < 2; i++) {
        int f = tid + i * 256;
        int kp = f >> 5, n4 = f & 31;
        int ka = kp >> 3;
        int pl = kp & 7;
        int slot = pl & 3;
        int regk = pl >> 2;
        float4 v0 = *(const float4*)(Bg + (size_t)(kp * 2) * D_ + n4 * 4);
        float4 v1 = *(const float4*)(Bg + (size_t)(kp * 2 + 1) * D_ + n4 * 4);
        const float* r0 = &v0.x;
        const float* r1 = &v1.x;
#pragma unroll
        for (int jj = 0; jj < 4; jj++) {
            int n = n4 * 4 + jj;
            uint32_t* dst = chunk + ((ka * 16 + (n >> 3)) << 6) +
                            ((n & 7) * 4 + slot) * 2 + regk;
            dst[0] = bf2(r0[jj], r1[jj]);
        }
    }
}

// ---------------- kernel 2: GEMM1  S = (ctx*w3) @ q^T + a + c  (bf16 mma) ---
// A-path: linear copy from g_ap fragments. B-path: q scatter (unchanged).
__global__ __launch_bounds__(256) void gemm1_tc(const float* __restrict__ q) {
    __shared__ uint32_t As[2 * 8 * 128];
    __shared__ uint32_t Bs[2 * 16 * 64];

    const int tid = threadIdx.x;
    const int b = blockIdx.z;
    const int mb = blockIdx.y;
    const int m0 = mb * 128;
    const int n0 = blockIdx.x * 128;
    const float* Bg = q + (size_t)b * J_ * D_;
    const uint4* Ap = (const uint4*)(g_ap + ((size_t)(b * 8 + mb) * 16) * 2048);

    const int lane = tid & 31;
    const int wid = tid >> 5;
    const int warp_m = wid & 1;
    const int warp_n = wid >> 1;

    float acc[4][4][4];
#pragma unroll
    for (int i = 0; i < 4; i++)
#pragma unroll
        for (int j = 0; j < 4; j++)
#pragma unroll
            for (int k = 0; k < 4; k++) acc[i][j][k] = 0.f;

    uint4 qa0 = Ap[tid], qa1 = Ap[256 + tid];
    float4 pb[4];
#pragma unroll
    for (int i = 0; i < 4; i++) {
        int f = tid + i * 256;
        int m = f >> 3, k4 = f & 7;
        pb[i] = *(const float4*)(Bg + (size_t)(n0 + m) * D_ + k4 * 4);
    }

    const int KT = D_ / 32;
    for (int kt = 0; kt < KT; kt++) {
        *(uint4*)&As[tid * 4] = qa0;
        *(uint4*)&As[1024 + tid * 4] = qa1;
#pragma unroll
        for (int i = 0; i < 4; i++) {
            int f = tid + i * 256;
            int m = f >> 3, k4 = f & 7;
            int ka = k4 >> 2;
            int kl = (k4 & 3) * 4;
            int slot = (kl >> 1) & 3;
            float4 v = pb[i];
            uint32_t* dst = Bs + ((ka * 16 + (m >> 3)) << 6) +
                            ((m & 7) * 4 + slot) * 2 + ((kl >= 8) ? 1 : 0);
            dst[0] = bf2(v.x, v.y);
            dst[2] = bf2(v.z, v.w);
        }
        __syncthreads();
        if (kt + 1 < KT) {
            qa0 = Ap[(kt + 1) * 512 + tid];
            qa1 = Ap[(kt + 1) * 512 + 256 + tid];
#pragma unroll
            for (int i = 0; i < 4; i++) {
                int f = tid + i * 256;
                int m = f >> 3, k4 = f & 7;
                pb[i] = *(const float4*)(Bg + (size_t)(n0 + m) * D_ + (kt + 1) * 32 + k4 * 4);
            }
        }
#pragma unroll
        for (int ka = 0; ka < 2; ka++) {
            uint32_t af[4][4], bf[4][2];
#pragma unroll
            for (int ma = 0; ma < 4; ma++)
                *(uint4*)af[ma] = *(const uint4*)&As[((ka * 8 + warp_m * 4 + ma) << 7) + lane * 4];
#pragma unroll
            for (int na = 0; na < 4; na++)
                *(uint2*)bf[na] = *(const uint2*)&Bs[((ka * 16 + warp_n * 4 + na) << 6) + lane * 2];
#pragma unroll
            for (int ma = 0; ma < 4; ma++)
#pragma unroll
                for (int na = 0; na < 4; na++) MMA_BF16(acc[ma][na], af[ma], bf[na]);
        }
        __syncthreads();
    }

    // epilogue: + a[b,m] + c[b,n]
    const int g = lane >> 2;
    const int tg = lane & 3;
#pragma unroll
    for (int ma = 0; ma < 4; ma++) {
        int r0 = m0 + warp_m * 64 + ma * 16 + g;
        float a0v = g_a[b * T_ + r0];
        float a1v = g_a[b * T_ + r0 + 8];
#pragma unroll
        for (int na = 0; na < 4; na++) {
            int n = n0 + warp_n * 32 + na * 8 + tg * 2;
            float c0 = g_c[b * J_ + n];
            float c1 = g_c[b * J_ + n + 1];
            float* p0 = g_S + (size_t)(b * T_ + r0) * J_ + n;
            *(float2*)p0 = make_float2(acc[ma][na][0] + a0v + c0, acc[ma][na][1] + a0v + c1);
            *(float2*)(p0 + 8 * J_) =
                make_float2(acc[ma][na][2] + a1v + c0, acc[ma][na][3] + a1v + c1);
        }
    }
}

// ---------------- kernel 3: e = exp(S), rowmax -> g_m, colsum partials ------
__global__ __launch_bounds__(256) void expred_kernel() {
    const int b = blockIdx.y;
    const int tb = blockIdx.x;  // 0..7
    const int lane = threadIdx.x & 31;
    const int wrp = threadIdx.x >> 5;
    float* S = g_S + (size_t)b * T_ * J_;
    __shared__ float csS[8][J_];

    float cs0[4] = {0.f, 0.f, 0.f, 0.f};
    float cs1[4] = {0.f, 0.f, 0.f, 0.f};
#pragma unroll 4
    for (int r = 0; r < 16; r++) {
        int t = tb * 128 + r * 8 + wrp;
        float* row = S + (size_t)t * J_;
        float4 v0 = *(float4*)(row + lane * 4);
        float4 v1 = *(float4*)(row + 128 + lane * 4);
        float mx = fmaxf(fmaxf(fmaxf(v0.x, v0.y), fmaxf(v0.z, v0.w)),
                         fmaxf(fmaxf(v1.x, v1.y), fmaxf(v1.z, v1.w)));
#pragma unroll
        for (int off = 16; off > 0; off >>= 1)
            mx = fmaxf(mx, __shfl_xor_sync(0xffffffffu, mx, off));
        if (lane == 0) g_m[b * T_ + t] = mx;
        float4 e0 = make_float4(__expf(v0.x), __expf(v0.y), __expf(v0.z), __expf(v0.w));
        float4 e1 = make_float4(__expf(v1.x), __expf(v1.y), __expf(v1.z), __expf(v1.w));
        *(float4*)(row + lane * 4) = e0;
        *(float4*)(row + 128 + lane * 4) = e1;
        cs0[0] += e0.x; cs0[1] += e0.y; cs0[2] += e0.z; cs0[3] += e0.w;
        cs1[0] += e1.x; cs1[1] += e1.y; cs1[2] += e1.z; cs1[3] += e1.w;
    }
#pragma unroll
    for (int i = 0; i < 4; i++) {
        csS[wrp][lane * 4 + i] = cs0[i];
        csS[wrp][128 + lane * 4 + i] = cs1[i];
    }
    __syncthreads();
    float s = 0.f;
#pragma unroll
    for (int wq = 0; wq < 8; wq++) s += csS[wq][threadIdx.x];
    g_zp[((size_t)b * 8 + tb) * J_ + threadIdx.x] = s;
}

// ---------------- kernel 3b: zinv = 1 / sum of partials ---------------------
__global__ __launch_bounds__(256) void zred_kernel() {
    const int b = blockIdx.x;
    const int j = threadIdx.x;
    float s = 0.f;
#pragma unroll
    for (int tb = 0; tb < 8; tb++) s += g_zp[((size_t)b * 8 + tb) * J_ + j];
    g_zinv[b * J_ + j] = 1.f / s;
}

// ---------------- kernel 4: b_t = softmax_t(rowmax) -------------------------
__global__ __launch_bounds__(256) void bt_kernel() {
    const int b = blockIdx.x;
    const int tid = threadIdx.x;
    const int lane = tid & 31;
    const int wid = tid >> 5;
    __shared__ float redA[8], redB[8];

    float4 v = ((const float4*)(g_m + b * T_))[tid];
    float mx = fmaxf(fmaxf(v.x, v.y), fmaxf(v.z, v.w));
#pragma unroll
    for (int off = 16; off > 0; off >>= 1) mx = fmaxf(mx, __shfl_xor_sync(0xffffffffu, mx, off));
    if (lane == 0) redA[wid] = mx;
    __syncthreads();
    float bm = redA[0];
#pragma unroll
    for (int w = 1; w < 8; w++) bm = fmaxf(bm, redA[w]);

    float e0 = __expf(v.x - bm), e1 = __expf(v.y - bm);
    float e2 = __expf(v.z - bm), e3 = __expf(v.w - bm);
    float s = e0 + e1 + e2 + e3;
#pragma unroll
    for (int off = 16; off > 0; off >>= 1) s += __shfl_xor_sync(0xffffffffu, s, off);
    if (lane == 0) redB[wid] = s;
    __syncthreads();
    float tot = 0.f;
#pragma unroll
    for (int w = 0; w < 8; w++) tot += redB[w];
    float inv = 1.f / tot;
    ((float4*)(g_bt + b * T_))[tid] = make_float4(e0 * inv, e1 * inv, e2 * inv, e3 * inv);
}

// ---------------- kernel 6: h[b,d] = sum_t bt * ctx -------------------------
__global__ __launch_bounds__(256) void h_kernel(const float* __restrict__ ctx) {
    const int b = blockIdx.y;
    const int d = blockIdx.x * 256 + threadIdx.x;
    __shared__ float bts[T_];
    for (int i = threadIdx.x; i < T_; i += 256) bts[i] = g_bt[b * T_ + i];
    __syncthreads();
    const float* cp = ctx + (size_t)b * T_ * D_ + d;
    float acc = 0.f;
#pragma unroll 4
    for (int t = 0; t < T_; t++) acc += bts[t] * cp[(size_t)t * D_];
    g_h[b * D_ + d] = acc;
}

// ---------------- kernel 7: GEMM2  U = (e*zinv) @ q, fused G assembly -------
// A = e with zinv folded (f32) at scatter; B-path: linear copy from g_qp.
__global__ __launch_bounds__(256) void gemm2_tc(const float* __restrict__ ctx,
                                                float* __restrict__ out) {
    __shared__ uint32_t As[2 * 8 * 128];
    __shared__ uint32_t Bs[2 * 16 * 64];
    __shared__ float zs[J_];

    const int tid = threadIdx.x;
    const int b = blockIdx.z;
    const int m0 = blockIdx.y * 128;
    const int nb = blockIdx.x;
    const float* Ag = g_S + (size_t)b * T_ * J_;  // e [1024][256]
    const uint4* Bp = (const uint4*)(g_qp + ((size_t)(b * 4 + nb) * 8) * 2048);

    const int lane = tid & 31;
    const int wid = tid >> 5;
    const int warp_m = wid & 1;
    const int warp_n = wid >> 1;

    zs[tid] = g_zinv[b * J_ + tid];

    float acc[4][4][4];
#pragma unroll
    for (int i = 0; i < 4; i++)
#pragma unroll
        for (int j = 0; j < 4; j++)
#pragma unroll
            for (int k = 0; k < 4; k++) acc[i][j][k] = 0.f;

    float4 pa[4];
    uint4 qb0 = Bp[tid], qb1 = Bp[256 + tid];
#pragma unroll
    for (int i = 0; i < 4; i++) {
        int f = tid + i * 256;
        int m = f >> 3, k4 = f & 7;
        pa[i] = *(const float4*)(Ag + (size_t)(m0 + m) * J_ + k4 * 4);
    }
    __syncthreads();  // zs ready

    const int KT = J_ / 32;
    for (int kt = 0; kt < KT; kt++) {
        // A scatter (zinv-folded f32, bf16 packed)
#pragma unroll
        for (int i = 0; i < 4; i++) {
            int f = tid + i * 256;
            int m = f >> 3, k4 = f & 7;
            int ka = k4 >> 2;
            int kl = (k4 & 3) * 4;
            int slot = (kl >> 1) & 3;
            float4 v = pa[i];
            const float* zp = zs + kt * 32 + k4 * 4;
            v.x *= zp[0]; v.y *= zp[1]; v.z *= zp[2]; v.w *= zp[3];
            int r = m & 15;
            uint32_t* dst = As + ((ka * 8 + (m >> 4)) << 7) +
                            ((r & 7) * 4 + slot) * 4 + (r >> 3) + ((kl >= 8) ? 2 : 0);
            dst[0] = bf2(v.x, v.y);
            dst[4] = bf2(v.z, v.w);
        }
        *(uint4*)&Bs[tid * 4] = qb0;
        *(uint4*)&Bs[1024 + tid * 4] = qb1;
        __syncthreads();
        if (kt + 1 < KT) {
#pragma unroll
            for (int i = 0; i < 4; i++) {
                int f = tid + i * 256;
                int m = f >> 3, k4 = f & 7;
                pa[i] = *(const float4*)(Ag + (size_t)(m0 + m) * J_ + (kt + 1) * 32 + k4 * 4);
            }
            qb0 = Bp[(kt + 1) * 512 + tid];
            qb1 = Bp[(kt + 1) * 512 + 256 + tid];
        }
#pragma unroll
        for (int ka = 0; ka < 2; ka++) {
            uint32_t af[4][4], bf[4][2];
#pragma unroll
            for (int ma = 0; ma < 4; ma++)
                *(uint4*)af[ma] = *(const uint4*)&As[((ka * 8 + warp_m * 4 + ma) << 7) + lane * 4];
#pragma unroll
            for (int na = 0; na < 4; na++)
                *(uint2*)bf[na] = *(const uint2*)&Bs[((ka * 16 + warp_n * 4 + na) << 6) + lane * 2];
#pragma unroll
            for (int ma = 0; ma < 4; ma++)
#pragma unroll
                for (int na = 0; na < 4; na++) MMA_BF16(acc[ma][na], af[ma], bf[na]);
        }
        __syncthreads();
    }

    // epilogue: G = [ctx | U | ctx*U | ctx*h]
    const int n0 = nb * 128;
    const int g = lane >> 2;
    const int tg = lane & 3;
#pragma unroll
    for (int ma = 0; ma < 4; ma++) {
        int r0 = m0 + warp_m * 64 + ma * 16 + g;
#pragma unroll
        for (int rr = 0; rr < 2; rr++) {
            int m = r0 + rr * 8;
            const float* crow = ctx + ((size_t)(b * T_ + m)) * D_;
            float* orow = out + ((size_t)(b * T_ + m)) * (4 * D_);
#pragma unroll
            for (int na = 0; na < 4; na++) {
                int n = n0 + warp_n * 32 + na * 8 + tg * 2;
                float2 cv = *(const float2*)(crow + n);
                float2 hv = *(const float2*)(g_h + b * D_ + n);
                float u0 = acc[ma][na][rr * 2 + 0];
                float u1 = acc[ma][na][rr * 2 + 1];
                *(float2*)(orow + n) = cv;
                *(float2*)(orow + D_ + n) = make_float2(u0, u1);
                *(float2*)(orow + 2 * D_ + n) = make_float2(cv.x * u0, cv.y * u1);
                *(float2*)(orow + 3 * D_ + n) = make_float2(cv.x * hv.x, cv.y * hv.y);
            }
        }
    }
}

// ---------------- launch -----------------------------------------------------
extern "C" void kernel_launch(void* const* d_in, const int* in_sizes, int n_in,
                              void* d_out, int out_size) {
    const float* ctx = (const float*)d_in[0];
    const float* q = (const float*)d_in[1];
    const float* w = (const float*)d_in[2];
    float* out = (float*)d_out;

    dotw_kernel<<<5120, 256>>>(ctx, q, w);
    apack_kernel<<<dim3(16, 8, 32), 256>>>(ctx, w);
    qpack_kernel<<<dim3(8, 4, 32), 256>>>(q);
    gemm1_tc<<<dim3(2, 8, 32), 256>>>(q);        // 4th launch: ncu capture slot
    expred_kernel<<<dim3(8, 32), 256>>>();
    zred_kernel<<<32, 256>>>();
    bt_kernel<<<32, 256>>>();
    h_kernel<<<dim3(2, 32), 256>>>(ctx);
    gemm2_tc<<<dim3(4, 8, 32), 256>>>(ctx, out);
}